// round 13
// baseline (speedup 1.0000x reference)
#include <cuda_runtime.h>
#include <cuda_fp16.h>
#include <math.h>
#include <stdint.h>

#define T_TOKENS   8192
#define DIM        1024
#define HIDDEN     2048
#define NEXP       8
#define TOPK       2
#define NROWS      (T_TOKENS * TOPK)   // 16384

#define BM 128
#define BN 128
#define BK 32                      // fp16 k-elements per stage
#define ROWB 80                    // padded row stride (64B data + 16B pad)
#define TILE_SZ (BM * ROWB)        // 10240 B per operand tile
#define STAGE   (2 * TILE_SZ)      // A, B
#define NSTAGE  4
#define SMEM_DYN (NSTAGE * STAGE)  // 81920 B
#define MAXTILES 136

// ---------------- scratch ----------------
__device__ __half g_w1h[(size_t)NEXP * HIDDEN * DIM];
__device__ __half g_w2h[(size_t)NEXP * DIM * HIDDEN];
__device__ __half g_xh[(size_t)T_TOKENS * DIM];
__device__ __half g_hh[(size_t)NROWS * HIDDEN];
__device__ float  g_ybuf[(size_t)NROWS * DIM];
__device__ int   g_counts[NEXP];
__device__ int   g_cursor[NEXP];
__device__ int   g_offsets[NEXP];
__device__ float g_psum[NEXP];
__device__ int   g_topk_idx[T_TOKENS * TOPK];
__device__ float g_topk_gate[T_TOKENS * TOPK];
__device__ int   g_row_token[NROWS];
__device__ int   g_token_row[T_TOKENS * TOPK];
__device__ int   g_tile_expert[MAXTILES];
__device__ int   g_tile_row[MAXTILES];
__device__ int   g_tile_m[MAXTILES];
__device__ int   g_ntiles;

// ---------------- helpers ----------------
__device__ __forceinline__ uint32_t s2u(const void* p) {
    uint32_t a;
    asm("{ .reg .u64 t; cvta.to.shared.u64 t, %1; cvt.u32.u64 %0, t; }" : "=r"(a) : "l"(p));
    return a;
}

#define LDSM4(r, addr) \
    asm volatile("ldmatrix.sync.aligned.m8n8.x4.shared.b16 {%0,%1,%2,%3}, [%4];" \
        : "=r"((r)[0]), "=r"((r)[1]), "=r"((r)[2]), "=r"((r)[3]) : "r"(addr) : "memory")

#define MMA16816F16(d, a, b0, b1) \
    asm volatile("mma.sync.aligned.m16n8k16.row.col.f32.f16.f16.f32 " \
        "{%0,%1,%2,%3}, {%4,%5,%6,%7}, {%8,%9}, {%0,%1,%2,%3};" \
        : "+f"((d)[0]), "+f"((d)[1]), "+f"((d)[2]), "+f"((d)[3]) \
        : "r"((a)[0]), "r"((a)[1]), "r"((a)[2]), "r"((a)[3]), "r"(b0), "r"(b1))

#define CPASYNC16(saddr, gptr, sz) \
    asm volatile("cp.async.cg.shared.global [%0], [%1], 16, %2;" \
        :: "r"(saddr), "l"(gptr), "r"(sz) : "memory")
#define CPCOMMIT() asm volatile("cp.async.commit_group;" ::: "memory")
#define CPWAIT2()  asm volatile("cp.async.wait_group 2;" ::: "memory")

__device__ __forceinline__ float gelu_exact(float v) {
    return 0.5f * v * (1.f + erff(v * 0.70710678118654752f));
}

// ---------------- convert fp32 -> fp16 (weights only; x handled in router) ----
// which: 0=w1, 1=w2
__global__ void conv_kernel(const float4* __restrict__ src, int which, int n4) {
    __half* dh = (which == 0) ? g_w1h : g_w2h;
    int stride = gridDim.x * blockDim.x;
    for (int i = blockIdx.x * blockDim.x + threadIdx.x; i < n4; i += stride) {
        float4 f = src[i];
        __half2 p0 = __floats2half2_rn(f.x, f.y);
        __half2 p1 = __floats2half2_rn(f.z, f.w);
        *(uint2*)(dh + (size_t)i * 4) =
            make_uint2(*(uint32_t*)&p0, *(uint32_t*)&p1);
    }
}

// ---------------- small kernels ----------------
__global__ void init_kernel() {
    int i = threadIdx.x;
    if (i < NEXP) { g_counts[i] = 0; g_cursor[i] = 0; g_psum[i] = 0.f; }
}

// router: logits/softmax/top-2 per token; ALSO converts this block's x rows to fp16
__global__ void router_kernel(const float* __restrict__ x,
                              const float* __restrict__ rw) {
    __shared__ float s_rw[NEXP * DIM];
    for (int i = threadIdx.x; i < NEXP * DIM; i += 256) s_rw[i] = rw[i];

    // fp16 copy of the 8 token rows this block owns (no separate conv-x pass)
    {
        const float4* xb = (const float4*)(x + (size_t)blockIdx.x * 8 * DIM);
        uint2* xh = (uint2*)(g_xh + (size_t)blockIdx.x * 8 * DIM);
        for (int i = threadIdx.x; i < 8 * DIM / 4; i += 256) {
            float4 f = xb[i];
            __half2 p0 = __floats2half2_rn(f.x, f.y);
            __half2 p1 = __floats2half2_rn(f.z, f.w);
            xh[i] = make_uint2(*(uint32_t*)&p0, *(uint32_t*)&p1);
        }
    }
    __syncthreads();

    int warp = threadIdx.x >> 5, lane = threadIdx.x & 31;
    int t = blockIdx.x * 8 + warp;
    const float* xr = x + (size_t)t * DIM;
    float acc[NEXP];
#pragma unroll
    for (int e = 0; e < NEXP; e++) acc[e] = 0.f;
    for (int j = lane; j < DIM; j += 32) {
        float xv = xr[j];
#pragma unroll
        for (int e = 0; e < NEXP; e++) acc[e] += xv * s_rw[e * DIM + j];
    }
#pragma unroll
    for (int e = 0; e < NEXP; e++)
#pragma unroll
        for (int o = 16; o > 0; o >>= 1)
            acc[e] += __shfl_down_sync(0xffffffff, acc[e], o);
    if (lane == 0) {
        float m = acc[0];
#pragma unroll
        for (int e = 1; e < NEXP; e++) m = fmaxf(m, acc[e]);
        float p[NEXP], s = 0.f;
#pragma unroll
        for (int e = 0; e < NEXP; e++) { p[e] = expf(acc[e] - m); s += p[e]; }
        float inv = 1.f / s;
#pragma unroll
        for (int e = 0; e < NEXP; e++) atomicAdd(&g_psum[e], p[e] * inv);
        int i1 = 0;
#pragma unroll
        for (int e = 1; e < NEXP; e++) if (acc[e] > acc[i1]) i1 = e;
        int i2 = (i1 == 0) ? 1 : 0;
#pragma unroll
        for (int e = 0; e < NEXP; e++)
            if (e != i1 && acc[e] > acc[i2]) i2 = e;
        float g1 = 1.f / (1.f + expf(acc[i2] - acc[i1]));
        float g2 = 1.f - g1;
        g_topk_idx[t*2+0] = i1;  g_topk_idx[t*2+1] = i2;
        g_topk_gate[t*2+0] = g1; g_topk_gate[t*2+1] = g2;
        atomicAdd(&g_counts[i1], 1);
        atomicAdd(&g_counts[i2], 1);
    }
}

__global__ void schedule_kernel(float* __restrict__ d_out, int write_aux) {
    if (threadIdx.x == 0) {
        int off = 0, nt = 0;
        for (int e = 0; e < NEXP; e++) {
            g_offsets[e] = off;
            int n = g_counts[e];
            for (int rs = 0; rs < n; rs += BM) {
                g_tile_expert[nt] = e;
                g_tile_row[nt]    = off + rs;
                g_tile_m[nt]      = min(BM, n - rs);
                nt++;
            }
            off += n;
        }
        g_ntiles = nt;
        if (write_aux) {
            float aux = 0.f;
            for (int e = 0; e < NEXP; e++)
                aux += ((float)g_counts[e] / (float)NROWS) * (g_psum[e] / (float)T_TOKENS);
            d_out[(size_t)T_TOKENS * DIM] = (float)NEXP * aux;
        }
    }
}

__global__ void scatter_kernel() {
    int t = blockIdx.x * 256 + threadIdx.x;
    if (t >= T_TOKENS) return;
#pragma unroll
    for (int k = 0; k < TOPK; k++) {
        int e   = g_topk_idx[t*2+k];
        int pos = atomicAdd(&g_cursor[e], 1);
        int r   = g_offsets[e] + pos;
        g_row_token[r]     = t;
        g_token_row[t*2+k] = r;
    }
}

// ---------------- grouped GEMM: mma.sync fp16, fp32 accum, cp.async 4-stage ----------------
// L1:  hidden = gelu(x @ w1^T + b1) -> g_hh (fp16)
// !L1: y      = hidden @ w2^T + b2  -> g_ybuf (fp32)
template <int KTOT, int NTOT, bool L1>
__global__ void __launch_bounds__(256, 2)
gemm_mma(const float* __restrict__ bias) {
    int tile = blockIdx.y;
    if (tile >= g_ntiles) return;
    int e     = g_tile_expert[tile];
    int row0  = g_tile_row[tile];
    int mrows = g_tile_m[tile];
    int n0    = blockIdx.x * BN;

    extern __shared__ char sm[];
    uint32_t sb = s2u(sm);

    int tid = threadIdx.x, lane = tid & 31, wid = tid >> 5;
    int wm = (wid & 1) * 64;
    int wn = (wid >> 1) * 32;

    const __half* A = L1 ? g_xh : g_hh;
    const __half* B = (L1 ? g_w1h : g_w2h) + ((size_t)e * NTOT + n0) * KTOT;
    const float* be = bias + (size_t)e * NTOT + n0;

    // per-thread cp.async items: 2 A row-chunks + 2 B row-chunks, 16B each
    size_t aoff[2], boff[2];
    uint32_t smoffA[2], smoffB[2];
    uint32_t asz[2];
#pragma unroll
    for (int t = 0; t < 2; t++) {
        int idx = tid + 256 * t;
        int r = idx >> 2, c = idx & 3;
        bool ok = (r < mrows);
        size_t rowbase;
        if (L1) rowbase = ok ? (size_t)g_row_token[row0 + r] * KTOT : 0;
        else    rowbase = ok ? (size_t)(row0 + r) * KTOT : 0;
        aoff[t]   = rowbase + c * 8;
        smoffA[t] = (uint32_t)(r * ROWB + c * 16);
        asz[t]    = ok ? 16u : 0u;   // zero-fill OOB rows
        boff[t]   = (size_t)r * KTOT + c * 8;
        smoffB[t] = smoffA[t];
    }

    auto issue_stage = [&](int s, int kc) {
        int k0 = kc * BK;
        uint32_t base = sb + s * STAGE;
#pragma unroll
        for (int t = 0; t < 2; t++) {
            CPASYNC16(base + smoffA[t],           A + aoff[t] + k0, asz[t]);
            CPASYNC16(base + TILE_SZ + smoffB[t], B + boff[t] + k0, 16u);
        }
    };

    float acc[4][4][4];
#pragma unroll
    for (int i = 0; i < 4; i++)
#pragma unroll
        for (int j = 0; j < 4; j++)
#pragma unroll
            for (int q = 0; q < 4; q++) acc[i][j][q] = 0.f;

    auto compute = [&](int s) {
        uint32_t Ab = sb + s * STAGE;
#pragma unroll
        for (int h = 0; h < 2; h++) {       // two k16 halves of BK=32
            int cb = 2 * h + (lane >> 4);
            int rA = wm + (lane & 15);
            uint32_t ah[4][4];
#pragma unroll
            for (int i = 0; i < 4; i++) {
                uint32_t ad = Ab + (uint32_t)((rA + i * 16) * ROWB + cb * 16);
                LDSM4(ah[i], ad);
            }
            int rB = wn + (lane & 15);
            uint32_t bh[2][4];
#pragma unroll
            for (int j = 0; j < 2; j++) {
                uint32_t bd = Ab + TILE_SZ +
                              (uint32_t)((rB + j * 16) * ROWB + cb * 16);
                LDSM4(bh[j], bd);
            }
#pragma unroll
            for (int i = 0; i < 4; i++)
#pragma unroll
                for (int j = 0; j < 4; j++) {
                    int jj = j >> 1, ss = j & 1;
                    MMA16816F16(acc[i][j], ah[i], bh[jj][ss], bh[jj][ss + 2]);
                }
        }
    };

    constexpr int NC = KTOT / BK;
    issue_stage(0, 0); CPCOMMIT();
    issue_stage(1, 1); CPCOMMIT();
    issue_stage(2, 2); CPCOMMIT();
    for (int c = 0; c < NC; c++) {
        CPWAIT2();
        __syncthreads();
        compute(c % NSTAGE);
        if (c + 3 < NC) issue_stage((c + 3) % NSTAGE, c + 3);
        CPCOMMIT();
    }

    // ---- epilogue: bias (+gelu for L1), direct register -> gmem ----
#pragma unroll
    for (int j = 0; j < 4; j++) {
        int colw = wn + j * 8 + 2 * (lane & 3);
        float b0 = __ldg(be + colw);
        float b1 = __ldg(be + colw + 1);
#pragma unroll
        for (int i = 0; i < 4; i++) {
#pragma unroll
            for (int rh = 0; rh < 2; rh++) {
                int m = wm + i * 16 + (lane >> 2) + rh * 8;
                if (m >= mrows) continue;
                float v0 = acc[i][j][rh * 2 + 0] + b0;
                float v1 = acc[i][j][rh * 2 + 1] + b1;
                size_t gbase = (size_t)(row0 + m) * NTOT + n0 + colw;
                if (L1) {
                    v0 = gelu_exact(v0);
                    v1 = gelu_exact(v1);
                    __half2 p = __floats2half2_rn(v0, v1);
                    *(uint32_t*)(g_hh + gbase) = *(uint32_t*)&p;
                } else {
                    *(float2*)(g_ybuf + gbase) = make_float2(v0, v1);
                }
            }
        }
    }
}

// ---------------- deterministic gated combine (vectorized) ----------------
__global__ void combine_kernel(float* __restrict__ out) {
    int t = blockIdx.x;
    int r0 = g_token_row[t*2+0], r1 = g_token_row[t*2+1];
    float g0 = g_topk_gate[t*2+0], g1 = g_topk_gate[t*2+1];
    const float4* y0 = (const float4*)(g_ybuf + (size_t)r0 * DIM);
    const float4* y1 = (const float4*)(g_ybuf + (size_t)r1 * DIM);
    float4* o = (float4*)(out + (size_t)t * DIM);
    int c = threadIdx.x;              // 256 threads x float4 = 1024 elems
    float4 a = y0[c], b = y1[c];
    o[c] = make_float4(g0 * a.x + g1 * b.x, g0 * a.y + g1 * b.y,
                       g0 * a.z + g1 * b.z, g0 * a.w + g1 * b.w);
}

// ---------------- launch ----------------
extern "C" void kernel_launch(void* const* d_in, const int* in_sizes, int n_in,
                              void* d_out, int out_size) {
    const float* x  = (const float*)d_in[0];
    const float* rw = (const float*)d_in[1];
    const float* w1 = (const float*)d_in[2];
    const float* b1 = (const float*)d_in[3];
    const float* w2 = (const float*)d_in[4];
    const float* b2 = (const float*)d_in[5];
    float* out = (float*)d_out;

    int write_aux = (out_size > T_TOKENS * DIM) ? 1 : 0;

    // idempotent, capture-safe, no static guard (determinism rule)
    cudaFuncSetAttribute(gemm_mma<DIM, HIDDEN, true>,
                         cudaFuncAttributeMaxDynamicSharedMemorySize, SMEM_DYN);
    cudaFuncSetAttribute(gemm_mma<HIDDEN, DIM, false>,
                         cudaFuncAttributeMaxDynamicSharedMemorySize, SMEM_DYN);

    init_kernel<<<1, 32>>>();
    router_kernel<<<T_TOKENS / 8, 256>>>(x, rw);
    conv_kernel<<<592, 256>>>((const float4*)w1, 0, NEXP * HIDDEN * DIM / 4);
    conv_kernel<<<592, 256>>>((const float4*)w2, 1, NEXP * DIM * HIDDEN / 4);
    schedule_kernel<<<1, 32>>>(out, write_aux);
    scatter_kernel<<<(T_TOKENS + 255) / 256, 256>>>();
    gemm_mma<DIM, HIDDEN, true><<<dim3(HIDDEN / BN, MAXTILES), 256, SMEM_DYN>>>(b1);
    gemm_mma<HIDDEN, DIM, false><<<dim3(DIM / BN, MAXTILES), 256, SMEM_DYN>>>(b2);
    combine_kernel<<<T_TOKENS, 256>>>(out);
}

// round 14
// speedup vs baseline: 1.4151x; 1.4151x over previous
#include <cuda_runtime.h>
#include <cuda_fp16.h>
#include <math.h>
#include <stdint.h>

#define T_TOKENS   8192
#define DIM        1024
#define HIDDEN     2048
#define NEXP       8
#define TOPK       2
#define NROWS      (T_TOKENS * TOPK)   // 16384

#define BM 128
#define BN 128
#define BK 32                      // fp16 k-elements per stage
#define ROWB 80                    // padded row stride (64B data + 16B pad)
#define TILE_SZ (BM * ROWB)        // 10240 B per operand tile
#define STAGE   (2 * TILE_SZ)      // A, B
#define NSTAGE  3
#define SMEM_DYN (NSTAGE * STAGE)  // 61440 B
#define MAXTILES 136

// ---------------- scratch ----------------
__device__ __half g_w1h[(size_t)NEXP * HIDDEN * DIM];
__device__ __half g_w2h[(size_t)NEXP * DIM * HIDDEN];
__device__ __half g_xh[(size_t)T_TOKENS * DIM];
__device__ __half g_hh[(size_t)NROWS * HIDDEN];
__device__ float  g_ybuf[(size_t)NROWS * DIM];
__device__ int   g_counts[NEXP];
__device__ int   g_cursor[NEXP];
__device__ int   g_offsets[NEXP];
__device__ float g_psum[NEXP];
__device__ int   g_topk_idx[T_TOKENS * TOPK];
__device__ float g_topk_gate[T_TOKENS * TOPK];
__device__ int   g_row_token[NROWS];
__device__ int   g_token_row[T_TOKENS * TOPK];
__device__ int   g_tile_expert[MAXTILES];
__device__ int   g_tile_row[MAXTILES];
__device__ int   g_tile_m[MAXTILES];
__device__ int   g_ntiles;

// ---------------- helpers ----------------
__device__ __forceinline__ uint32_t s2u(const void* p) {
    uint32_t a;
    asm("{ .reg .u64 t; cvta.to.shared.u64 t, %1; cvt.u32.u64 %0, t; }" : "=r"(a) : "l"(p));
    return a;
}

#define LDSM4(r, addr) \
    asm volatile("ldmatrix.sync.aligned.m8n8.x4.shared.b16 {%0,%1,%2,%3}, [%4];" \
        : "=r"((r)[0]), "=r"((r)[1]), "=r"((r)[2]), "=r"((r)[3]) : "r"(addr) : "memory")

#define MMA16816F16(d, a, b0, b1) \
    asm volatile("mma.sync.aligned.m16n8k16.row.col.f32.f16.f16.f32 " \
        "{%0,%1,%2,%3}, {%4,%5,%6,%7}, {%8,%9}, {%0,%1,%2,%3};" \
        : "+f"((d)[0]), "+f"((d)[1]), "+f"((d)[2]), "+f"((d)[3]) \
        : "r"((a)[0]), "r"((a)[1]), "r"((a)[2]), "r"((a)[3]), "r"(b0), "r"(b1))

#define CPASYNC16(saddr, gptr, sz) \
    asm volatile("cp.async.cg.shared.global [%0], [%1], 16, %2;" \
        :: "r"(saddr), "l"(gptr), "r"(sz) : "memory")
#define CPCOMMIT() asm volatile("cp.async.commit_group;" ::: "memory")
#define CPWAIT1()  asm volatile("cp.async.wait_group 1;" ::: "memory")

__device__ __forceinline__ float gelu_exact(float v) {
    return 0.5f * v * (1.f + erff(v * 0.70710678118654752f));
}

// ---------------- convert fp32 -> fp16 (weights only; x handled in router) ----
// which: 0=w1, 1=w2
__global__ void conv_kernel(const float4* __restrict__ src, int which, int n4) {
    __half* dh = (which == 0) ? g_w1h : g_w2h;
    int stride = gridDim.x * blockDim.x;
    for (int i = blockIdx.x * blockDim.x + threadIdx.x; i < n4; i += stride) {
        float4 f = src[i];
        __half2 p0 = __floats2half2_rn(f.x, f.y);
        __half2 p1 = __floats2half2_rn(f.z, f.w);
        *(uint2*)(dh + (size_t)i * 4) =
            make_uint2(*(uint32_t*)&p0, *(uint32_t*)&p1);
    }
}

// ---------------- small kernels ----------------
__global__ void init_kernel() {
    int i = threadIdx.x;
    if (i < NEXP) { g_counts[i] = 0; g_cursor[i] = 0; g_psum[i] = 0.f; }
}

// router: logits/softmax/top-2 per token; ALSO converts this block's x rows to fp16
__global__ void router_kernel(const float* __restrict__ x,
                              const float* __restrict__ rw) {
    __shared__ float s_rw[NEXP * DIM];
    for (int i = threadIdx.x; i < NEXP * DIM; i += 256) s_rw[i] = rw[i];

    // fp16 copy of the 8 token rows this block owns (no separate conv-x pass)
    {
        const float4* xb = (const float4*)(x + (size_t)blockIdx.x * 8 * DIM);
        uint2* xh = (uint2*)(g_xh + (size_t)blockIdx.x * 8 * DIM);
        for (int i = threadIdx.x; i < 8 * DIM / 4; i += 256) {
            float4 f = xb[i];
            __half2 p0 = __floats2half2_rn(f.x, f.y);
            __half2 p1 = __floats2half2_rn(f.z, f.w);
            xh[i] = make_uint2(*(uint32_t*)&p0, *(uint32_t*)&p1);
        }
    }
    __syncthreads();

    int warp = threadIdx.x >> 5, lane = threadIdx.x & 31;
    int t = blockIdx.x * 8 + warp;
    const float* xr = x + (size_t)t * DIM;
    float acc[NEXP];
#pragma unroll
    for (int e = 0; e < NEXP; e++) acc[e] = 0.f;
    for (int j = lane; j < DIM; j += 32) {
        float xv = xr[j];
#pragma unroll
        for (int e = 0; e < NEXP; e++) acc[e] += xv * s_rw[e * DIM + j];
    }
#pragma unroll
    for (int e = 0; e < NEXP; e++)
#pragma unroll
        for (int o = 16; o > 0; o >>= 1)
            acc[e] += __shfl_down_sync(0xffffffff, acc[e], o);
    if (lane == 0) {
        float m = acc[0];
#pragma unroll
        for (int e = 1; e < NEXP; e++) m = fmaxf(m, acc[e]);
        float p[NEXP], s = 0.f;
#pragma unroll
        for (int e = 0; e < NEXP; e++) { p[e] = expf(acc[e] - m); s += p[e]; }
        float inv = 1.f / s;
#pragma unroll
        for (int e = 0; e < NEXP; e++) atomicAdd(&g_psum[e], p[e] * inv);
        int i1 = 0;
#pragma unroll
        for (int e = 1; e < NEXP; e++) if (acc[e] > acc[i1]) i1 = e;
        int i2 = (i1 == 0) ? 1 : 0;
#pragma unroll
        for (int e = 0; e < NEXP; e++)
            if (e != i1 && acc[e] > acc[i2]) i2 = e;
        float g1 = 1.f / (1.f + expf(acc[i2] - acc[i1]));
        float g2 = 1.f - g1;
        g_topk_idx[t*2+0] = i1;  g_topk_idx[t*2+1] = i2;
        g_topk_gate[t*2+0] = g1; g_topk_gate[t*2+1] = g2;
        atomicAdd(&g_counts[i1], 1);
        atomicAdd(&g_counts[i2], 1);
    }
}

__global__ void schedule_kernel(float* __restrict__ d_out, int write_aux) {
    if (threadIdx.x == 0) {
        int off = 0, nt = 0;
        for (int e = 0; e < NEXP; e++) {
            g_offsets[e] = off;
            int n = g_counts[e];
            for (int rs = 0; rs < n; rs += BM) {
                g_tile_expert[nt] = e;
                g_tile_row[nt]    = off + rs;
                g_tile_m[nt]      = min(BM, n - rs);
                nt++;
            }
            off += n;
        }
        g_ntiles = nt;
        if (write_aux) {
            float aux = 0.f;
            for (int e = 0; e < NEXP; e++)
                aux += ((float)g_counts[e] / (float)NROWS) * (g_psum[e] / (float)T_TOKENS);
            d_out[(size_t)T_TOKENS * DIM] = (float)NEXP * aux;
        }
    }
}

__global__ void scatter_kernel() {
    int t = blockIdx.x * 256 + threadIdx.x;
    if (t >= T_TOKENS) return;
#pragma unroll
    for (int k = 0; k < TOPK; k++) {
        int e   = g_topk_idx[t*2+k];
        int pos = atomicAdd(&g_cursor[e], 1);
        int r   = g_offsets[e] + pos;
        g_row_token[r]     = t;
        g_token_row[t*2+k] = r;
    }
}

// ---------------- grouped GEMM: mma.sync fp16, fp32 accum, cp.async 3-stage ----------------
// (R12-verified mainloop: NSTAGE=3, wait_group 1, prefetch distance 2)
// L1:  hidden = gelu(x @ w1^T + b1) -> g_hh (fp16)
// !L1: y      = hidden @ w2^T + b2  -> g_ybuf (fp32)
template <int KTOT, int NTOT, bool L1>
__global__ void __launch_bounds__(256, 2)
gemm_mma(const float* __restrict__ bias) {
    int tile = blockIdx.y;
    if (tile >= g_ntiles) return;
    int e     = g_tile_expert[tile];
    int row0  = g_tile_row[tile];
    int mrows = g_tile_m[tile];
    int n0    = blockIdx.x * BN;

    extern __shared__ char sm[];
    uint32_t sb = s2u(sm);

    int tid = threadIdx.x, lane = tid & 31, wid = tid >> 5;
    int wm = (wid & 1) * 64;
    int wn = (wid >> 1) * 32;

    const __half* A = L1 ? g_xh : g_hh;
    const __half* B = (L1 ? g_w1h : g_w2h) + ((size_t)e * NTOT + n0) * KTOT;
    const float* be = bias + (size_t)e * NTOT + n0;

    // per-thread cp.async items: 2 A row-chunks + 2 B row-chunks, 16B each
    size_t aoff[2], boff[2];
    uint32_t smoffA[2], smoffB[2];
    uint32_t asz[2];
#pragma unroll
    for (int t = 0; t < 2; t++) {
        int idx = tid + 256 * t;
        int r = idx >> 2, c = idx & 3;
        bool ok = (r < mrows);
        size_t rowbase;
        if (L1) rowbase = ok ? (size_t)g_row_token[row0 + r] * KTOT : 0;
        else    rowbase = ok ? (size_t)(row0 + r) * KTOT : 0;
        aoff[t]   = rowbase + c * 8;
        smoffA[t] = (uint32_t)(r * ROWB + c * 16);
        asz[t]    = ok ? 16u : 0u;   // zero-fill OOB rows
        boff[t]   = (size_t)r * KTOT + c * 8;
        smoffB[t] = smoffA[t];
    }

    auto issue_stage = [&](int s, int kc) {
        int k0 = kc * BK;
        uint32_t base = sb + s * STAGE;
#pragma unroll
        for (int t = 0; t < 2; t++) {
            CPASYNC16(base + smoffA[t],           A + aoff[t] + k0, asz[t]);
            CPASYNC16(base + TILE_SZ + smoffB[t], B + boff[t] + k0, 16u);
        }
    };

    float acc[4][4][4];
#pragma unroll
    for (int i = 0; i < 4; i++)
#pragma unroll
        for (int j = 0; j < 4; j++)
#pragma unroll
            for (int q = 0; q < 4; q++) acc[i][j][q] = 0.f;

    auto compute = [&](int s) {
        uint32_t Ab = sb + s * STAGE;
#pragma unroll
        for (int h = 0; h < 2; h++) {       // two k16 halves of BK=32
            int cb = 2 * h + (lane >> 4);
            int rA = wm + (lane & 15);
            uint32_t ah[4][4];
#pragma unroll
            for (int i = 0; i < 4; i++) {
                uint32_t ad = Ab + (uint32_t)((rA + i * 16) * ROWB + cb * 16);
                LDSM4(ah[i], ad);
            }
            int rB = wn + (lane & 15);
            uint32_t bh[2][4];
#pragma unroll
            for (int j = 0; j < 2; j++) {
                uint32_t bd = Ab + TILE_SZ +
                              (uint32_t)((rB + j * 16) * ROWB + cb * 16);
                LDSM4(bh[j], bd);
            }
#pragma unroll
            for (int i = 0; i < 4; i++)
#pragma unroll
                for (int j = 0; j < 4; j++) {
                    int jj = j >> 1, ss = j & 1;
                    MMA16816F16(acc[i][j], ah[i], bh[jj][ss], bh[jj][ss + 2]);
                }
        }
    };

    constexpr int NC = KTOT / BK;
    issue_stage(0, 0); CPCOMMIT();
    issue_stage(1, 1); CPCOMMIT();
    for (int c = 0; c < NC; c++) {
        CPWAIT1();
        __syncthreads();
        compute(c % NSTAGE);
        if (c + 2 < NC) issue_stage((c + 2) % NSTAGE, c + 2);
        CPCOMMIT();
    }

    // ---- epilogue: bias (+gelu for L1), direct register -> gmem ----
#pragma unroll
    for (int j = 0; j < 4; j++) {
        int colw = wn + j * 8 + 2 * (lane & 3);
        float b0 = __ldg(be + colw);
        float b1 = __ldg(be + colw + 1);
#pragma unroll
        for (int i = 0; i < 4; i++) {
#pragma unroll
            for (int rh = 0; rh < 2; rh++) {
                int m = wm + i * 16 + (lane >> 2) + rh * 8;
                if (m >= mrows) continue;
                float v0 = acc[i][j][rh * 2 + 0] + b0;
                float v1 = acc[i][j][rh * 2 + 1] + b1;
                size_t gbase = (size_t)(row0 + m) * NTOT + n0 + colw;
                if (L1) {
                    v0 = gelu_exact(v0);
                    v1 = gelu_exact(v1);
                    __half2 p = __floats2half2_rn(v0, v1);
                    *(uint32_t*)(g_hh + gbase) = *(uint32_t*)&p;
                } else {
                    *(float2*)(g_ybuf + gbase) = make_float2(v0, v1);
                }
            }
        }
    }
}

// ---------------- deterministic gated combine (vectorized) ----------------
__global__ void combine_kernel(float* __restrict__ out) {
    int t = blockIdx.x;
    int r0 = g_token_row[t*2+0], r1 = g_token_row[t*2+1];
    float g0 = g_topk_gate[t*2+0], g1 = g_topk_gate[t*2+1];
    const float4* y0 = (const float4*)(g_ybuf + (size_t)r0 * DIM);
    const float4* y1 = (const float4*)(g_ybuf + (size_t)r1 * DIM);
    float4* o = (float4*)(out + (size_t)t * DIM);
    int c = threadIdx.x;              // 256 threads x float4 = 1024 elems
    float4 a = y0[c], b = y1[c];
    o[c] = make_float4(g0 * a.x + g1 * b.x, g0 * a.y + g1 * b.y,
                       g0 * a.z + g1 * b.z, g0 * a.w + g1 * b.w);
}

// ---------------- launch ----------------
extern "C" void kernel_launch(void* const* d_in, const int* in_sizes, int n_in,
                              void* d_out, int out_size) {
    const float* x  = (const float*)d_in[0];
    const float* rw = (const float*)d_in[1];
    const float* w1 = (const float*)d_in[2];
    const float* b1 = (const float*)d_in[3];
    const float* w2 = (const float*)d_in[4];
    const float* b2 = (const float*)d_in[5];
    float* out = (float*)d_out;

    int write_aux = (out_size > T_TOKENS * DIM) ? 1 : 0;

    // idempotent, capture-safe, no static guard (determinism rule)
    cudaFuncSetAttribute(gemm_mma<DIM, HIDDEN, true>,
                         cudaFuncAttributeMaxDynamicSharedMemorySize, SMEM_DYN);
    cudaFuncSetAttribute(gemm_mma<HIDDEN, DIM, false>,
                         cudaFuncAttributeMaxDynamicSharedMemorySize, SMEM_DYN);

    init_kernel<<<1, 32>>>();
    router_kernel<<<T_TOKENS / 8, 256>>>(x, rw);
    conv_kernel<<<592, 256>>>((const float4*)w1, 0, NEXP * HIDDEN * DIM / 4);
    conv_kernel<<<592, 256>>>((const float4*)w2, 1, NEXP * DIM * HIDDEN / 4);
    schedule_kernel<<<1, 32>>>(out, write_aux);
    scatter_kernel<<<(T_TOKENS + 255) / 256, 256>>>();
    gemm_mma<DIM, HIDDEN, true><<<dim3(HIDDEN / BN, MAXTILES), 256, SMEM_DYN>>>(b1);
    gemm_mma<HIDDEN, DIM, false><<<dim3(DIM / BN, MAXTILES), 256, SMEM_DYN>>>(b2);
    combine_kernel<<<T_TOKENS, 256>>>(out);
}

// round 15
// speedup vs baseline: 1.4662x; 1.0361x over previous
#include <cuda_runtime.h>
#include <cuda_fp16.h>
#include <math.h>
#include <stdint.h>

#define T_TOKENS   8192
#define DIM        1024
#define HIDDEN     2048
#define NEXP       8
#define TOPK       2
#define NROWS      (T_TOKENS * TOPK)   // 16384

#define BM 128
#define BN 128
#define BK 32                      // fp16 k-elements per stage
#define ROWB 80                    // padded row stride (64B data + 16B pad)
#define TILE_SZ (BM * ROWB)        // 10240 B per operand tile
#define STAGE   (2 * TILE_SZ)      // A, B
#define NSTAGE  3
#define SMEM_DYN (NSTAGE * STAGE)  // 61440 B
#define MAXTILES 136

// ---------------- scratch ----------------
__device__ __half g_w1h[(size_t)NEXP * HIDDEN * DIM];
__device__ __half g_w2h[(size_t)NEXP * DIM * HIDDEN];
__device__ __half g_xh[(size_t)T_TOKENS * DIM];
__device__ __half g_hh[(size_t)NROWS * HIDDEN];
__device__ __half g_yh[(size_t)NROWS * DIM];        // fp16 y (was fp32)
__device__ int   g_counts[NEXP];
__device__ int   g_cursor[NEXP];
__device__ int   g_offsets[NEXP];
__device__ float g_psum[NEXP];
__device__ int   g_topk_idx[T_TOKENS * TOPK];
__device__ float g_topk_gate[T_TOKENS * TOPK];
__device__ int   g_row_token[NROWS];
__device__ int   g_token_row[T_TOKENS * TOPK];
__device__ int   g_tile_expert[MAXTILES];
__device__ int   g_tile_row[MAXTILES];
__device__ int   g_tile_m[MAXTILES];
__device__ int   g_ntiles;

// ---------------- helpers ----------------
__device__ __forceinline__ uint32_t s2u(const void* p) {
    uint32_t a;
    asm("{ .reg .u64 t; cvta.to.shared.u64 t, %1; cvt.u32.u64 %0, t; }" : "=r"(a) : "l"(p));
    return a;
}

#define LDSM4(r, addr) \
    asm volatile("ldmatrix.sync.aligned.m8n8.x4.shared.b16 {%0,%1,%2,%3}, [%4];" \
        : "=r"((r)[0]), "=r"((r)[1]), "=r"((r)[2]), "=r"((r)[3]) : "r"(addr) : "memory")

#define MMA16816F16(d, a, b0, b1) \
    asm volatile("mma.sync.aligned.m16n8k16.row.col.f32.f16.f16.f32 " \
        "{%0,%1,%2,%3}, {%4,%5,%6,%7}, {%8,%9}, {%0,%1,%2,%3};" \
        : "+f"((d)[0]), "+f"((d)[1]), "+f"((d)[2]), "+f"((d)[3]) \
        : "r"((a)[0]), "r"((a)[1]), "r"((a)[2]), "r"((a)[3]), "r"(b0), "r"(b1))

#define CPASYNC16(saddr, gptr, sz) \
    asm volatile("cp.async.cg.shared.global [%0], [%1], 16, %2;" \
        :: "r"(saddr), "l"(gptr), "r"(sz) : "memory")
#define CPCOMMIT() asm volatile("cp.async.commit_group;" ::: "memory")
#define CPWAIT1()  asm volatile("cp.async.wait_group 1;" ::: "memory")

__device__ __forceinline__ float gelu_exact(float v) {
    return 0.5f * v * (1.f + erff(v * 0.70710678118654752f));
}

// ---------------- convert fp32 -> fp16 (weights; x handled in router) --------
// which: 0=w1, 1=w2
__global__ void conv_kernel(const float4* __restrict__ src, int which, int n4) {
    __half* dh = (which == 0) ? g_w1h : g_w2h;
    int stride = gridDim.x * blockDim.x;
    for (int i = blockIdx.x * blockDim.x + threadIdx.x; i < n4; i += stride) {
        float4 f = src[i];
        __half2 p0 = __floats2half2_rn(f.x, f.y);
        __half2 p1 = __floats2half2_rn(f.z, f.w);
        *(uint2*)(dh + (size_t)i * 4) =
            make_uint2(*(uint32_t*)&p0, *(uint32_t*)&p1);
    }
}

// ---------------- small kernels ----------------
__global__ void init_kernel() {
    int i = threadIdx.x;
    if (i < NEXP) { g_counts[i] = 0; g_cursor[i] = 0; g_psum[i] = 0.f; }
}

// router: logits/softmax/top-2 per token; ALSO converts this block's x rows to fp16
__global__ void router_kernel(const float* __restrict__ x,
                              const float* __restrict__ rw) {
    __shared__ float s_rw[NEXP * DIM];
    for (int i = threadIdx.x; i < NEXP * DIM; i += 256) s_rw[i] = rw[i];

    // fp16 copy of the 8 token rows this block owns (no separate conv-x pass)
    {
        const float4* xb = (const float4*)(x + (size_t)blockIdx.x * 8 * DIM);
        uint2* xh = (uint2*)(g_xh + (size_t)blockIdx.x * 8 * DIM);
        for (int i = threadIdx.x; i < 8 * DIM / 4; i += 256) {
            float4 f = xb[i];
            __half2 p0 = __floats2half2_rn(f.x, f.y);
            __half2 p1 = __floats2half2_rn(f.z, f.w);
            xh[i] = make_uint2(*(uint32_t*)&p0, *(uint32_t*)&p1);
        }
    }
    __syncthreads();

    int warp = threadIdx.x >> 5, lane = threadIdx.x & 31;
    int t = blockIdx.x * 8 + warp;
    const float* xr = x + (size_t)t * DIM;
    float acc[NEXP];
#pragma unroll
    for (int e = 0; e < NEXP; e++) acc[e] = 0.f;
    for (int j = lane; j < DIM; j += 32) {
        float xv = xr[j];
#pragma unroll
        for (int e = 0; e < NEXP; e++) acc[e] += xv * s_rw[e * DIM + j];
    }
#pragma unroll
    for (int e = 0; e < NEXP; e++)
#pragma unroll
        for (int o = 16; o > 0; o >>= 1)
            acc[e] += __shfl_down_sync(0xffffffff, acc[e], o);
    if (lane == 0) {
        float m = acc[0];
#pragma unroll
        for (int e = 1; e < NEXP; e++) m = fmaxf(m, acc[e]);
        float p[NEXP], s = 0.f;
#pragma unroll
        for (int e = 0; e < NEXP; e++) { p[e] = expf(acc[e] - m); s += p[e]; }
        float inv = 1.f / s;
#pragma unroll
        for (int e = 0; e < NEXP; e++) atomicAdd(&g_psum[e], p[e] * inv);
        int i1 = 0;
#pragma unroll
        for (int e = 1; e < NEXP; e++) if (acc[e] > acc[i1]) i1 = e;
        int i2 = (i1 == 0) ? 1 : 0;
#pragma unroll
        for (int e = 0; e < NEXP; e++)
            if (e != i1 && acc[e] > acc[i2]) i2 = e;
        float g1 = 1.f / (1.f + expf(acc[i2] - acc[i1]));
        float g2 = 1.f - g1;
        g_topk_idx[t*2+0] = i1;  g_topk_idx[t*2+1] = i2;
        g_topk_gate[t*2+0] = g1; g_topk_gate[t*2+1] = g2;
        atomicAdd(&g_counts[i1], 1);
        atomicAdd(&g_counts[i2], 1);
    }
}

__global__ void schedule_kernel(float* __restrict__ d_out, int write_aux) {
    if (threadIdx.x == 0) {
        int off = 0, nt = 0;
        for (int e = 0; e < NEXP; e++) {
            g_offsets[e] = off;
            int n = g_counts[e];
            for (int rs = 0; rs < n; rs += BM) {
                g_tile_expert[nt] = e;
                g_tile_row[nt]    = off + rs;
                g_tile_m[nt]      = min(BM, n - rs);
                nt++;
            }
            off += n;
        }
        g_ntiles = nt;
        if (write_aux) {
            float aux = 0.f;
            for (int e = 0; e < NEXP; e++)
                aux += ((float)g_counts[e] / (float)NROWS) * (g_psum[e] / (float)T_TOKENS);
            d_out[(size_t)T_TOKENS * DIM] = (float)NEXP * aux;
        }
    }
}

__global__ void scatter_kernel() {
    int t = blockIdx.x * 256 + threadIdx.x;
    if (t >= T_TOKENS) return;
#pragma unroll
    for (int k = 0; k < TOPK; k++) {
        int e   = g_topk_idx[t*2+k];
        int pos = atomicAdd(&g_cursor[e], 1);
        int r   = g_offsets[e] + pos;
        g_row_token[r]     = t;
        g_token_row[t*2+k] = r;
    }
}

// ---------------- grouped GEMM: mma.sync fp16, fp32 accum, cp.async 3-stage ----------------
// (R12/R14-verified mainloop: NSTAGE=3, wait_group 1, prefetch distance 2 — DO NOT TOUCH)
// L1:  hidden = gelu(x @ w1^T + b1) -> g_hh (fp16)
// !L1: y      = hidden @ w2^T + b2  -> g_yh (fp16)
template <int KTOT, int NTOT, bool L1>
__global__ void __launch_bounds__(256, 2)
gemm_mma(const float* __restrict__ bias) {
    int tile = blockIdx.y;
    if (tile >= g_ntiles) return;
    int e     = g_tile_expert[tile];
    int row0  = g_tile_row[tile];
    int mrows = g_tile_m[tile];
    int n0    = blockIdx.x * BN;

    extern __shared__ char sm[];
    uint32_t sb = s2u(sm);

    int tid = threadIdx.x, lane = tid & 31, wid = tid >> 5;
    int wm = (wid & 1) * 64;
    int wn = (wid >> 1) * 32;

    const __half* A = L1 ? g_xh : g_hh;
    const __half* B = (L1 ? g_w1h : g_w2h) + ((size_t)e * NTOT + n0) * KTOT;
    const float* be = bias + (size_t)e * NTOT + n0;

    // per-thread cp.async items: 2 A row-chunks + 2 B row-chunks, 16B each
    size_t aoff[2], boff[2];
    uint32_t smoffA[2], smoffB[2];
    uint32_t asz[2];
#pragma unroll
    for (int t = 0; t < 2; t++) {
        int idx = tid + 256 * t;
        int r = idx >> 2, c = idx & 3;
        bool ok = (r < mrows);
        size_t rowbase;
        if (L1) rowbase = ok ? (size_t)g_row_token[row0 + r] * KTOT : 0;
        else    rowbase = ok ? (size_t)(row0 + r) * KTOT : 0;
        aoff[t]   = rowbase + c * 8;
        smoffA[t] = (uint32_t)(r * ROWB + c * 16);
        asz[t]    = ok ? 16u : 0u;   // zero-fill OOB rows
        boff[t]   = (size_t)r * KTOT + c * 8;
        smoffB[t] = smoffA[t];
    }

    auto issue_stage = [&](int s, int kc) {
        int k0 = kc * BK;
        uint32_t base = sb + s * STAGE;
#pragma unroll
        for (int t = 0; t < 2; t++) {
            CPASYNC16(base + smoffA[t],           A + aoff[t] + k0, asz[t]);
            CPASYNC16(base + TILE_SZ + smoffB[t], B + boff[t] + k0, 16u);
        }
    };

    float acc[4][4][4];
#pragma unroll
    for (int i = 0; i < 4; i++)
#pragma unroll
        for (int j = 0; j < 4; j++)
#pragma unroll
            for (int q = 0; q < 4; q++) acc[i][j][q] = 0.f;

    auto compute = [&](int s) {
        uint32_t Ab = sb + s * STAGE;
#pragma unroll
        for (int h = 0; h < 2; h++) {       // two k16 halves of BK=32
            int cb = 2 * h + (lane >> 4);
            int rA = wm + (lane & 15);
            uint32_t ah[4][4];
#pragma unroll
            for (int i = 0; i < 4; i++) {
                uint32_t ad = Ab + (uint32_t)((rA + i * 16) * ROWB + cb * 16);
                LDSM4(ah[i], ad);
            }
            int rB = wn + (lane & 15);
            uint32_t bh[2][4];
#pragma unroll
            for (int j = 0; j < 2; j++) {
                uint32_t bd = Ab + TILE_SZ +
                              (uint32_t)((rB + j * 16) * ROWB + cb * 16);
                LDSM4(bh[j], bd);
            }
#pragma unroll
            for (int i = 0; i < 4; i++)
#pragma unroll
                for (int j = 0; j < 4; j++) {
                    int jj = j >> 1, ss = j & 1;
                    MMA16816F16(acc[i][j], ah[i], bh[jj][ss], bh[jj][ss + 2]);
                }
        }
    };

    constexpr int NC = KTOT / BK;
    issue_stage(0, 0); CPCOMMIT();
    issue_stage(1, 1); CPCOMMIT();
    for (int c = 0; c < NC; c++) {
        CPWAIT1();
        __syncthreads();
        compute(c % NSTAGE);
        if (c + 2 < NC) issue_stage((c + 2) % NSTAGE, c + 2);
        CPCOMMIT();
    }

    // ---- epilogue: bias (+gelu for L1), direct register -> gmem ----
#pragma unroll
    for (int j = 0; j < 4; j++) {
        int colw = wn + j * 8 + 2 * (lane & 3);
        float b0 = __ldg(be + colw);
        float b1 = __ldg(be + colw + 1);
#pragma unroll
        for (int i = 0; i < 4; i++) {
#pragma unroll
            for (int rh = 0; rh < 2; rh++) {
                int m = wm + i * 16 + (lane >> 2) + rh * 8;
                if (m >= mrows) continue;
                float v0 = acc[i][j][rh * 2 + 0] + b0;
                float v1 = acc[i][j][rh * 2 + 1] + b1;
                size_t gbase = (size_t)(row0 + m) * NTOT + n0 + colw;
                if (L1) {
                    v0 = gelu_exact(v0);
                    v1 = gelu_exact(v1);
                    __half2 p = __floats2half2_rn(v0, v1);
                    *(uint32_t*)(g_hh + gbase) = *(uint32_t*)&p;
                } else {
                    __half2 p = __floats2half2_rn(v0, v1);
                    *(uint32_t*)(g_yh + gbase) = *(uint32_t*)&p;
                }
            }
        }
    }
}

// ---------------- deterministic gated combine (fp16 y, vectorized) ----------
__global__ void combine_kernel(float* __restrict__ out) {
    int t = blockIdx.x;
    int r0 = g_token_row[t*2+0], r1 = g_token_row[t*2+1];
    float g0 = g_topk_gate[t*2+0], g1 = g_topk_gate[t*2+1];
    const uint2* y0 = (const uint2*)(g_yh + (size_t)r0 * DIM);
    const uint2* y1 = (const uint2*)(g_yh + (size_t)r1 * DIM);
    float4* o = (float4*)(out + (size_t)t * DIM);
    int c = threadIdx.x;              // 256 threads x 4 halves = 1024 elems
    uint2 a = y0[c], b = y1[c];
    float2 a0 = __half22float2(*(__half2*)&a.x);
    float2 a1 = __half22float2(*(__half2*)&a.y);
    float2 b0 = __half22float2(*(__half2*)&b.x);
    float2 b1 = __half22float2(*(__half2*)&b.y);
    o[c] = make_float4(g0 * a0.x + g1 * b0.x, g0 * a0.y + g1 * b0.y,
                       g0 * a1.x + g1 * b1.x, g0 * a1.y + g1 * b1.y);
}

// ---------------- launch ----------------
extern "C" void kernel_launch(void* const* d_in, const int* in_sizes, int n_in,
                              void* d_out, int out_size) {
    const float* x  = (const float*)d_in[0];
    const float* rw = (const float*)d_in[1];
    const float* w1 = (const float*)d_in[2];
    const float* b1 = (const float*)d_in[3];
    const float* w2 = (const float*)d_in[4];
    const float* b2 = (const float*)d_in[5];
    float* out = (float*)d_out;

    int write_aux = (out_size > T_TOKENS * DIM) ? 1 : 0;

    // idempotent, capture-safe, no static guard (determinism rule)
    cudaFuncSetAttribute(gemm_mma<DIM, HIDDEN, true>,
                         cudaFuncAttributeMaxDynamicSharedMemorySize, SMEM_DYN);
    cudaFuncSetAttribute(gemm_mma<HIDDEN, DIM, false>,
                         cudaFuncAttributeMaxDynamicSharedMemorySize, SMEM_DYN);

    // fork-join: weight conversions on a side stream, overlapped with the
    // router/schedule/scatter chain (no data dependency between them).
    // Stream/event objects are host-side (no device memory); created and
    // destroyed every call. Falls back to serial if creation fails.
    cudaStream_t side = 0;
    cudaEvent_t ev_fork = 0, ev_join = 0;
    bool forked =
        (cudaStreamCreateWithFlags(&side, cudaStreamNonBlocking) == cudaSuccess) &&
        (cudaEventCreateWithFlags(&ev_fork, cudaEventDisableTiming) == cudaSuccess) &&
        (cudaEventCreateWithFlags(&ev_join, cudaEventDisableTiming) == cudaSuccess);

    if (forked) {
        cudaEventRecord(ev_fork, 0);            // fork from (capturing) default stream
        cudaStreamWaitEvent(side, ev_fork, 0);
        conv_kernel<<<592, 256, 0, side>>>((const float4*)w1, 0, NEXP * HIDDEN * DIM / 4);
        conv_kernel<<<592, 256, 0, side>>>((const float4*)w2, 1, NEXP * DIM * HIDDEN / 4);
        cudaEventRecord(ev_join, side);
    } else {
        conv_kernel<<<592, 256>>>((const float4*)w1, 0, NEXP * HIDDEN * DIM / 4);
        conv_kernel<<<592, 256>>>((const float4*)w2, 1, NEXP * DIM * HIDDEN / 4);
    }

    init_kernel<<<1, 32>>>();
    router_kernel<<<T_TOKENS / 8, 256>>>(x, rw);
    schedule_kernel<<<1, 32>>>(out, write_aux);
    scatter_kernel<<<(T_TOKENS + 255) / 256, 256>>>();

    if (forked) cudaStreamWaitEvent(0, ev_join, 0);   // join before L1

    gemm_mma<DIM, HIDDEN, true><<<dim3(HIDDEN / BN, MAXTILES), 256, SMEM_DYN>>>(b1);
    gemm_mma<HIDDEN, DIM, false><<<dim3(DIM / BN, MAXTILES), 256, SMEM_DYN>>>(b2);
    combine_kernel<<<T_TOKENS, 256>>>(out);

    if (side)    cudaStreamDestroy(side);
    if (ev_fork) cudaEventDestroy(ev_fork);
    if (ev_join) cudaEventDestroy(ev_join);
}

// round 16
// speedup vs baseline: 1.6602x; 1.1324x over previous
#include <cuda_runtime.h>
#include <cuda_fp16.h>
#include <math.h>
#include <stdint.h>

#define T_TOKENS   8192
#define DIM        1024
#define HIDDEN     2048
#define NEXP       8
#define TOPK       2
#define NROWS      (T_TOKENS * TOPK)   // 16384

#define BM 128
#define BN 128
#define BK 32                      // fp16 k-elements per stage
#define ROWB 80                    // padded row stride (64B data + 16B pad)
#define TILE_SZ (BM * ROWB)        // 10240 B per operand tile
#define STAGE   (2 * TILE_SZ)      // A, B
#define NSTAGE  3
#define SMEM_DYN (NSTAGE * STAGE)  // 61440 B
#define MAXTILES 136

// ---------------- scratch ----------------
__device__ __half g_w1h[(size_t)NEXP * HIDDEN * DIM];
__device__ __half g_w2h[(size_t)NEXP * DIM * HIDDEN];
__device__ __half g_xh[(size_t)T_TOKENS * DIM];
__device__ __half g_hh[(size_t)NROWS * HIDDEN];
__device__ __half g_yh[(size_t)NROWS * DIM];
__device__ int   g_counts[NEXP];
__device__ int   g_cursor[NEXP];
__device__ int   g_offsets[NEXP];
__device__ float g_psum[NEXP];
__device__ int   g_topk_idx[T_TOKENS * TOPK];
__device__ float g_topk_gate[T_TOKENS * TOPK];
__device__ int   g_row_token[NROWS];
__device__ int   g_token_row[T_TOKENS * TOPK];
__device__ int   g_tile_expert[MAXTILES];
__device__ int   g_tile_row[MAXTILES];
__device__ int   g_tile_m[MAXTILES];
__device__ int   g_ntiles;

// ---------------- helpers ----------------
__device__ __forceinline__ uint32_t s2u(const void* p) {
    uint32_t a;
    asm("{ .reg .u64 t; cvta.to.shared.u64 t, %1; cvt.u32.u64 %0, t; }" : "=r"(a) : "l"(p));
    return a;
}

#define LDSM4(r, addr) \
    asm volatile("ldmatrix.sync.aligned.m8n8.x4.shared.b16 {%0,%1,%2,%3}, [%4];" \
        : "=r"((r)[0]), "=r"((r)[1]), "=r"((r)[2]), "=r"((r)[3]) : "r"(addr) : "memory")

#define MMA16816F16(d, a, b0, b1) \
    asm volatile("mma.sync.aligned.m16n8k16.row.col.f32.f16.f16.f32 " \
        "{%0,%1,%2,%3}, {%4,%5,%6,%7}, {%8,%9}, {%0,%1,%2,%3};" \
        : "+f"((d)[0]), "+f"((d)[1]), "+f"((d)[2]), "+f"((d)[3]) \
        : "r"((a)[0]), "r"((a)[1]), "r"((a)[2]), "r"((a)[3]), "r"(b0), "r"(b1))

#define CPASYNC16(saddr, gptr, sz) \
    asm volatile("cp.async.cg.shared.global [%0], [%1], 16, %2;" \
        :: "r"(saddr), "l"(gptr), "r"(sz) : "memory")
#define CPCOMMIT() asm volatile("cp.async.commit_group;" ::: "memory")
#define CPWAIT1()  asm volatile("cp.async.wait_group 1;" ::: "memory")

__device__ __forceinline__ float gelu_exact(float v) {
    return 0.5f * v * (1.f + erff(v * 0.70710678118654752f));
}

// ---------------- convert fp32 -> fp16 (weights; x handled in router) --------
// which: 0=w1, 1=w2
__global__ void conv_kernel(const float4* __restrict__ src, int which, int n4) {
    __half* dh = (which == 0) ? g_w1h : g_w2h;
    int stride = gridDim.x * blockDim.x;
    for (int i = blockIdx.x * blockDim.x + threadIdx.x; i < n4; i += stride) {
        float4 f = src[i];
        __half2 p0 = __floats2half2_rn(f.x, f.y);
        __half2 p1 = __floats2half2_rn(f.z, f.w);
        *(uint2*)(dh + (size_t)i * 4) =
            make_uint2(*(uint32_t*)&p0, *(uint32_t*)&p1);
    }
}

// ---------------- small kernels ----------------
__global__ void init_kernel() {
    int i = threadIdx.x;
    if (i < NEXP) { g_counts[i] = 0; g_cursor[i] = 0; g_psum[i] = 0.f; }
}

// router: ONE fused float4 pass per token row: convert x->fp16 AND accumulate
// the 8 expert logits; block-level psum reduction before the global atomic.
__global__ void router_kernel(const float* __restrict__ x,
                              const float* __restrict__ rw) {
    __shared__ float4 s_rw4[NEXP * DIM / 4];   // 32 KB
    __shared__ float  s_p[NEXP];
    for (int i = threadIdx.x; i < NEXP * DIM / 4; i += 256)
        s_rw4[i] = ((const float4*)rw)[i];
    if (threadIdx.x < NEXP) s_p[threadIdx.x] = 0.f;
    __syncthreads();

    int warp = threadIdx.x >> 5, lane = threadIdx.x & 31;
    int t = blockIdx.x * 8 + warp;
    const float4* xr4 = (const float4*)(x + (size_t)t * DIM);
    uint2* xh = (uint2*)(g_xh + (size_t)t * DIM);

    float acc[NEXP];
#pragma unroll
    for (int e = 0; e < NEXP; e++) acc[e] = 0.f;

#pragma unroll
    for (int i = 0; i < DIM / 4 / 32; i++) {   // 8 iterations
        int j = lane + 32 * i;
        float4 f = xr4[j];
        __half2 p0 = __floats2half2_rn(f.x, f.y);
        __half2 p1 = __floats2half2_rn(f.z, f.w);
        xh[j] = make_uint2(*(uint32_t*)&p0, *(uint32_t*)&p1);
#pragma unroll
        for (int e = 0; e < NEXP; e++) {
            float4 w = s_rw4[e * (DIM / 4) + j];
            acc[e] += f.x * w.x + f.y * w.y + f.z * w.z + f.w * w.w;
        }
    }
#pragma unroll
    for (int e = 0; e < NEXP; e++)
#pragma unroll
        for (int o = 16; o > 0; o >>= 1)
            acc[e] += __shfl_down_sync(0xffffffff, acc[e], o);

    if (lane == 0) {
        float m = acc[0];
#pragma unroll
        for (int e = 1; e < NEXP; e++) m = fmaxf(m, acc[e]);
        float p[NEXP], s = 0.f;
#pragma unroll
        for (int e = 0; e < NEXP; e++) { p[e] = expf(acc[e] - m); s += p[e]; }
        float inv = 1.f / s;
#pragma unroll
        for (int e = 0; e < NEXP; e++) atomicAdd(&s_p[e], p[e] * inv);

        int i1 = 0;
#pragma unroll
        for (int e = 1; e < NEXP; e++) if (acc[e] > acc[i1]) i1 = e;
        int i2 = (i1 == 0) ? 1 : 0;
#pragma unroll
        for (int e = 0; e < NEXP; e++)
            if (e != i1 && acc[e] > acc[i2]) i2 = e;
        float g1 = 1.f / (1.f + expf(acc[i2] - acc[i1]));
        float g2 = 1.f - g1;
        g_topk_idx[t*2+0] = i1;  g_topk_idx[t*2+1] = i2;
        g_topk_gate[t*2+0] = g1; g_topk_gate[t*2+1] = g2;
        atomicAdd(&g_counts[i1], 1);
        atomicAdd(&g_counts[i2], 1);
    }
    __syncthreads();
    if (threadIdx.x < NEXP) atomicAdd(&g_psum[threadIdx.x], s_p[threadIdx.x]);
}

__global__ void schedule_kernel(float* __restrict__ d_out, int write_aux) {
    if (threadIdx.x == 0) {
        int off = 0, nt = 0;
        for (int e = 0; e < NEXP; e++) {
            g_offsets[e] = off;
            int n = g_counts[e];
            for (int rs = 0; rs < n; rs += BM) {
                g_tile_expert[nt] = e;
                g_tile_row[nt]    = off + rs;
                g_tile_m[nt]      = min(BM, n - rs);
                nt++;
            }
            off += n;
        }
        g_ntiles = nt;
        if (write_aux) {
            float aux = 0.f;
            for (int e = 0; e < NEXP; e++)
                aux += ((float)g_counts[e] / (float)NROWS) * (g_psum[e] / (float)T_TOKENS);
            d_out[(size_t)T_TOKENS * DIM] = (float)NEXP * aux;
        }
    }
}

__global__ void scatter_kernel() {
    int t = blockIdx.x * 256 + threadIdx.x;
    if (t >= T_TOKENS) return;
#pragma unroll
    for (int k = 0; k < TOPK; k++) {
        int e   = g_topk_idx[t*2+k];
        int pos = atomicAdd(&g_cursor[e], 1);
        int r   = g_offsets[e] + pos;
        g_row_token[r]     = t;
        g_token_row[t*2+k] = r;
    }
}

// ---------------- grouped GEMM: mma.sync fp16, fp32 accum, cp.async 3-stage ----------------
// (R12/R14-verified mainloop: NSTAGE=3, wait_group 1, prefetch distance 2 — DO NOT TOUCH)
// L1:  hidden = gelu(x @ w1^T + b1) -> g_hh (fp16)
// !L1: y      = hidden @ w2^T + b2  -> g_yh (fp16)
template <int KTOT, int NTOT, bool L1>
__global__ void __launch_bounds__(256, 2)
gemm_mma(const float* __restrict__ bias) {
    int tile = blockIdx.y;
    if (tile >= g_ntiles) return;
    int e     = g_tile_expert[tile];
    int row0  = g_tile_row[tile];
    int mrows = g_tile_m[tile];
    int n0    = blockIdx.x * BN;

    extern __shared__ char sm[];
    uint32_t sb = s2u(sm);

    int tid = threadIdx.x, lane = tid & 31, wid = tid >> 5;
    int wm = (wid & 1) * 64;
    int wn = (wid >> 1) * 32;

    const __half* A = L1 ? g_xh : g_hh;
    const __half* B = (L1 ? g_w1h : g_w2h) + ((size_t)e * NTOT + n0) * KTOT;
    const float* be = bias + (size_t)e * NTOT + n0;

    // per-thread cp.async items: 2 A row-chunks + 2 B row-chunks, 16B each
    size_t aoff[2], boff[2];
    uint32_t smoffA[2], smoffB[2];
    uint32_t asz[2];
#pragma unroll
    for (int t = 0; t < 2; t++) {
        int idx = tid + 256 * t;
        int r = idx >> 2, c = idx & 3;
        bool ok = (r < mrows);
        size_t rowbase;
        if (L1) rowbase = ok ? (size_t)g_row_token[row0 + r] * KTOT : 0;
        else    rowbase = ok ? (size_t)(row0 + r) * KTOT : 0;
        aoff[t]   = rowbase + c * 8;
        smoffA[t] = (uint32_t)(r * ROWB + c * 16);
        asz[t]    = ok ? 16u : 0u;   // zero-fill OOB rows
        boff[t]   = (size_t)r * KTOT + c * 8;
        smoffB[t] = smoffA[t];
    }

    auto issue_stage = [&](int s, int kc) {
        int k0 = kc * BK;
        uint32_t base = sb + s * STAGE;
#pragma unroll
        for (int t = 0; t < 2; t++) {
            CPASYNC16(base + smoffA[t],           A + aoff[t] + k0, asz[t]);
            CPASYNC16(base + TILE_SZ + smoffB[t], B + boff[t] + k0, 16u);
        }
    };

    float acc[4][4][4];
#pragma unroll
    for (int i = 0; i < 4; i++)
#pragma unroll
        for (int j = 0; j < 4; j++)
#pragma unroll
            for (int q = 0; q < 4; q++) acc[i][j][q] = 0.f;

    auto compute = [&](int s) {
        uint32_t Ab = sb + s * STAGE;
#pragma unroll
        for (int h = 0; h < 2; h++) {       // two k16 halves of BK=32
            int cb = 2 * h + (lane >> 4);
            int rA = wm + (lane & 15);
            uint32_t ah[4][4];
#pragma unroll
            for (int i = 0; i < 4; i++) {
                uint32_t ad = Ab + (uint32_t)((rA + i * 16) * ROWB + cb * 16);
                LDSM4(ah[i], ad);
            }
            int rB = wn + (lane & 15);
            uint32_t bh[2][4];
#pragma unroll
            for (int j = 0; j < 2; j++) {
                uint32_t bd = Ab + TILE_SZ +
                              (uint32_t)((rB + j * 16) * ROWB + cb * 16);
                LDSM4(bh[j], bd);
            }
#pragma unroll
            for (int i = 0; i < 4; i++)
#pragma unroll
                for (int j = 0; j < 4; j++) {
                    int jj = j >> 1, ss = j & 1;
                    MMA16816F16(acc[i][j], ah[i], bh[jj][ss], bh[jj][ss + 2]);
                }
        }
    };

    constexpr int NC = KTOT / BK;
    issue_stage(0, 0); CPCOMMIT();
    issue_stage(1, 1); CPCOMMIT();
    for (int c = 0; c < NC; c++) {
        CPWAIT1();
        __syncthreads();
        compute(c % NSTAGE);
        if (c + 2 < NC) issue_stage((c + 2) % NSTAGE, c + 2);
        CPCOMMIT();
    }

    // ---- epilogue: bias (+gelu for L1), direct register -> gmem ----
#pragma unroll
    for (int j = 0; j < 4; j++) {
        int colw = wn + j * 8 + 2 * (lane & 3);
        float b0 = __ldg(be + colw);
        float b1 = __ldg(be + colw + 1);
#pragma unroll
        for (int i = 0; i < 4; i++) {
#pragma unroll
            for (int rh = 0; rh < 2; rh++) {
                int m = wm + i * 16 + (lane >> 2) + rh * 8;
                if (m >= mrows) continue;
                float v0 = acc[i][j][rh * 2 + 0] + b0;
                float v1 = acc[i][j][rh * 2 + 1] + b1;
                size_t gbase = (size_t)(row0 + m) * NTOT + n0 + colw;
                if (L1) {
                    v0 = gelu_exact(v0);
                    v1 = gelu_exact(v1);
                    __half2 p = __floats2half2_rn(v0, v1);
                    *(uint32_t*)(g_hh + gbase) = *(uint32_t*)&p;
                } else {
                    __half2 p = __floats2half2_rn(v0, v1);
                    *(uint32_t*)(g_yh + gbase) = *(uint32_t*)&p;
                }
            }
        }
    }
}

// ---------------- deterministic gated combine (fp16 y, vectorized) ----------
__global__ void combine_kernel(float* __restrict__ out) {
    int t = blockIdx.x;
    int r0 = g_token_row[t*2+0], r1 = g_token_row[t*2+1];
    float g0 = g_topk_gate[t*2+0], g1 = g_topk_gate[t*2+1];
    const uint2* y0 = (const uint2*)(g_yh + (size_t)r0 * DIM);
    const uint2* y1 = (const uint2*)(g_yh + (size_t)r1 * DIM);
    float4* o = (float4*)(out + (size_t)t * DIM);
    int c = threadIdx.x;              // 256 threads x 4 halves = 1024 elems
    uint2 a = y0[c], b = y1[c];
    float2 a0 = __half22float2(*(__half2*)&a.x);
    float2 a1 = __half22float2(*(__half2*)&a.y);
    float2 b0 = __half22float2(*(__half2*)&b.x);
    float2 b1 = __half22float2(*(__half2*)&b.y);
    o[c] = make_float4(g0 * a0.x + g1 * b0.x, g0 * a0.y + g1 * b0.y,
                       g0 * a1.x + g1 * b1.x, g0 * a1.y + g1 * b1.y);
}

// ---------------- launch ----------------
extern "C" void kernel_launch(void* const* d_in, const int* in_sizes, int n_in,
                              void* d_out, int out_size) {
    const float* x  = (const float*)d_in[0];
    const float* rw = (const float*)d_in[1];
    const float* w1 = (const float*)d_in[2];
    const float* b1 = (const float*)d_in[3];
    const float* w2 = (const float*)d_in[4];
    const float* b2 = (const float*)d_in[5];
    float* out = (float*)d_out;

    int write_aux = (out_size > T_TOKENS * DIM) ? 1 : 0;

    // idempotent, capture-safe, no static guard (determinism rule)
    cudaFuncSetAttribute(gemm_mma<DIM, HIDDEN, true>,
                         cudaFuncAttributeMaxDynamicSharedMemorySize, SMEM_DYN);
    cudaFuncSetAttribute(gemm_mma<HIDDEN, DIM, false>,
                         cudaFuncAttributeMaxDynamicSharedMemorySize, SMEM_DYN);

    // fork-join: weight conversions on a side stream, overlapped with the
    // router/schedule/scatter chain. Host-side objects only; serial fallback.
    cudaStream_t side = 0;
    cudaEvent_t ev_fork = 0, ev_join = 0;
    bool forked =
        (cudaStreamCreateWithFlags(&side, cudaStreamNonBlocking) == cudaSuccess) &&
        (cudaEventCreateWithFlags(&ev_fork, cudaEventDisableTiming) == cudaSuccess) &&
        (cudaEventCreateWithFlags(&ev_join, cudaEventDisableTiming) == cudaSuccess);

    if (forked) {
        cudaEventRecord(ev_fork, 0);
        cudaStreamWaitEvent(side, ev_fork, 0);
        conv_kernel<<<592, 256, 0, side>>>((const float4*)w1, 0, NEXP * HIDDEN * DIM / 4);
        conv_kernel<<<592, 256, 0, side>>>((const float4*)w2, 1, NEXP * DIM * HIDDEN / 4);
        cudaEventRecord(ev_join, side);
    } else {
        conv_kernel<<<592, 256>>>((const float4*)w1, 0, NEXP * HIDDEN * DIM / 4);
        conv_kernel<<<592, 256>>>((const float4*)w2, 1, NEXP * DIM * HIDDEN / 4);
    }

    init_kernel<<<1, 32>>>();
    router_kernel<<<T_TOKENS / 8, 256>>>(x, rw);
    schedule_kernel<<<1, 32>>>(out, write_aux);
    scatter_kernel<<<(T_TOKENS + 255) / 256, 256>>>();

    if (forked) cudaStreamWaitEvent(0, ev_join, 0);   // join before L1

    gemm_mma<DIM, HIDDEN, true><<<dim3(HIDDEN / BN, MAXTILES), 256, SMEM_DYN>>>(b1);
    gemm_mma<HIDDEN, DIM, false><<<dim3(DIM / BN, MAXTILES), 256, SMEM_DYN>>>(b2);
    combine_kernel<<<T_TOKENS, 256>>>(out);

    if (side)    cudaStreamDestroy(side);
    if (ev_fork) cudaEventDestroy(ev_fork);
    if (ev_join) cudaEventDestroy(ev_join);
}

// round 17
// speedup vs baseline: 1.6854x; 1.0152x over previous
#include <cuda_runtime.h>
#include <cuda_fp16.h>
#include <math.h>
#include <stdint.h>

#define T_TOKENS   8192
#define DIM        1024
#define HIDDEN     2048
#define NEXP       8
#define TOPK       2
#define NROWS      (T_TOKENS * TOPK)   // 16384

#define BM 128
#define BN 128
#define BK 32                      // fp16 k-elements per stage
#define ROWB 80                    // padded row stride (64B data + 16B pad)
#define TILE_SZ (BM * ROWB)        // 10240 B per operand tile
#define STAGE   (2 * TILE_SZ)      // A, B
#define NSTAGE  3
#define SMEM_DYN (NSTAGE * STAGE)  // 61440 B
#define MAXTILES 136

#define RT_BLK  512                // router threads (16 tokens/block)
#define RT_TOK  16
#define RT_GRID (T_TOKENS / RT_TOK)   // 512

// ---------------- scratch ----------------
__device__ __half g_w1h[(size_t)NEXP * HIDDEN * DIM];
__device__ __half g_w2h[(size_t)NEXP * DIM * HIDDEN];
__device__ __half g_xh[(size_t)T_TOKENS * DIM];
__device__ __half g_hh[(size_t)NROWS * HIDDEN];
__device__ __half g_yh[(size_t)NROWS * DIM];
__device__ int   g_counts[NEXP];
__device__ int   g_cursor[NEXP];
__device__ int   g_offsets[NEXP];
__device__ float g_psum[NEXP];
__device__ int   g_done;
__device__ int   g_topk_idx[T_TOKENS * TOPK];
__device__ float g_topk_gate[T_TOKENS * TOPK];
__device__ int   g_row_token[NROWS];
__device__ int   g_token_row[T_TOKENS * TOPK];
__device__ int   g_tile_expert[MAXTILES];
__device__ int   g_tile_row[MAXTILES];
__device__ int   g_tile_m[MAXTILES];
__device__ int   g_ntiles;

// ---------------- helpers ----------------
__device__ __forceinline__ uint32_t s2u(const void* p) {
    uint32_t a;
    asm("{ .reg .u64 t; cvta.to.shared.u64 t, %1; cvt.u32.u64 %0, t; }" : "=r"(a) : "l"(p));
    return a;
}

#define LDSM4(r, addr) \
    asm volatile("ldmatrix.sync.aligned.m8n8.x4.shared.b16 {%0,%1,%2,%3}, [%4];" \
        : "=r"((r)[0]), "=r"((r)[1]), "=r"((r)[2]), "=r"((r)[3]) : "r"(addr) : "memory")

#define MMA16816F16(d, a, b0, b1) \
    asm volatile("mma.sync.aligned.m16n8k16.row.col.f32.f16.f16.f32 " \
        "{%0,%1,%2,%3}, {%4,%5,%6,%7}, {%8,%9}, {%0,%1,%2,%3};" \
        : "+f"((d)[0]), "+f"((d)[1]), "+f"((d)[2]), "+f"((d)[3]) \
        : "r"((a)[0]), "r"((a)[1]), "r"((a)[2]), "r"((a)[3]), "r"(b0), "r"(b1))

#define CPASYNC16(saddr, gptr, sz) \
    asm volatile("cp.async.cg.shared.global [%0], [%1], 16, %2;" \
        :: "r"(saddr), "l"(gptr), "r"(sz) : "memory")
#define CPCOMMIT() asm volatile("cp.async.commit_group;" ::: "memory")
#define CPWAIT1()  asm volatile("cp.async.wait_group 1;" ::: "memory")

__device__ __forceinline__ float gelu_exact(float v) {
    return 0.5f * v * (1.f + erff(v * 0.70710678118654752f));
}

// ---------------- convert fp32 -> fp16 (weights; x handled in router) --------
__global__ void conv_kernel(const float4* __restrict__ src, int which, int n4) {
    __half* dh = (which == 0) ? g_w1h : g_w2h;
    int stride = gridDim.x * blockDim.x;
    for (int i = blockIdx.x * blockDim.x + threadIdx.x; i < n4; i += stride) {
        float4 f = src[i];
        __half2 p0 = __floats2half2_rn(f.x, f.y);
        __half2 p1 = __floats2half2_rn(f.z, f.w);
        *(uint2*)(dh + (size_t)i * 4) =
            make_uint2(*(uint32_t*)&p0, *(uint32_t*)&p1);
    }
}

// ---------------- small kernels ----------------
__global__ void init_kernel() {
    int i = threadIdx.x;
    if (i < NEXP) { g_counts[i] = 0; g_cursor[i] = 0; g_psum[i] = 0.f; }
    if (i == 0) g_done = 0;
}

// router: fused x->fp16 conversion + logits; 16 tokens/block (full occupancy);
// last block (threadfence + ticket) performs the schedule step deterministically.
__global__ void __launch_bounds__(RT_BLK)
router_kernel(const float* __restrict__ x, const float* __restrict__ rw,
              float* __restrict__ d_out, int write_aux) {
    __shared__ float4 s_rw4[NEXP * DIM / 4];   // 32 KB
    __shared__ float  s_p[NEXP];
    for (int i = threadIdx.x; i < NEXP * DIM / 4; i += RT_BLK)
        s_rw4[i] = ((const float4*)rw)[i];
    if (threadIdx.x < NEXP) s_p[threadIdx.x] = 0.f;
    __syncthreads();

    int warp = threadIdx.x >> 5, lane = threadIdx.x & 31;
    int t = blockIdx.x * RT_TOK + warp;
    const float4* xr4 = (const float4*)(x + (size_t)t * DIM);
    uint2* xh = (uint2*)(g_xh + (size_t)t * DIM);

    float acc[NEXP];
#pragma unroll
    for (int e = 0; e < NEXP; e++) acc[e] = 0.f;

#pragma unroll
    for (int i = 0; i < DIM / 4 / 32; i++) {   // 8 iterations
        int j = lane + 32 * i;
        float4 f = xr4[j];
        __half2 p0 = __floats2half2_rn(f.x, f.y);
        __half2 p1 = __floats2half2_rn(f.z, f.w);
        xh[j] = make_uint2(*(uint32_t*)&p0, *(uint32_t*)&p1);
#pragma unroll
        for (int e = 0; e < NEXP; e++) {
            float4 w = s_rw4[e * (DIM / 4) + j];
            acc[e] += f.x * w.x + f.y * w.y + f.z * w.z + f.w * w.w;
        }
    }
#pragma unroll
    for (int e = 0; e < NEXP; e++)
#pragma unroll
        for (int o = 16; o > 0; o >>= 1)
            acc[e] += __shfl_down_sync(0xffffffff, acc[e], o);

    if (lane == 0) {
        float m = acc[0];
#pragma unroll
        for (int e = 1; e < NEXP; e++) m = fmaxf(m, acc[e]);
        float p[NEXP], s = 0.f;
#pragma unroll
        for (int e = 0; e < NEXP; e++) { p[e] = expf(acc[e] - m); s += p[e]; }
        float inv = 1.f / s;
#pragma unroll
        for (int e = 0; e < NEXP; e++) atomicAdd(&s_p[e], p[e] * inv);

        int i1 = 0;
#pragma unroll
        for (int e = 1; e < NEXP; e++) if (acc[e] > acc[i1]) i1 = e;
        int i2 = (i1 == 0) ? 1 : 0;
#pragma unroll
        for (int e = 0; e < NEXP; e++)
            if (e != i1 && acc[e] > acc[i2]) i2 = e;
        float g1 = 1.f / (1.f + expf(acc[i2] - acc[i1]));
        float g2 = 1.f - g1;
        g_topk_idx[t*2+0] = i1;  g_topk_idx[t*2+1] = i2;
        g_topk_gate[t*2+0] = g1; g_topk_gate[t*2+1] = g2;
        atomicAdd(&g_counts[i1], 1);
        atomicAdd(&g_counts[i2], 1);
    }
    __syncthreads();
    if (threadIdx.x < NEXP) atomicAdd(&g_psum[threadIdx.x], s_p[threadIdx.x]);

    // ---- last block performs schedule (values deterministic: all counts done)
    if (threadIdx.x == 0) {
        __threadfence();
        int prev = atomicAdd(&g_done, 1);
        if (prev == (int)gridDim.x - 1) {
            __threadfence();   // order reads after all blocks' fenced writes
            int off = 0, nt = 0;
            for (int e = 0; e < NEXP; e++) {
                g_offsets[e] = off;
                int n = g_counts[e];
                for (int rs = 0; rs < n; rs += BM) {
                    g_tile_expert[nt] = e;
                    g_tile_row[nt]    = off + rs;
                    g_tile_m[nt]      = min(BM, n - rs);
                    nt++;
                }
                off += n;
            }
            g_ntiles = nt;
            if (write_aux) {
                float aux = 0.f;
                for (int e = 0; e < NEXP; e++)
                    aux += ((float)g_counts[e] / (float)NROWS) *
                           (g_psum[e] / (float)T_TOKENS);
                d_out[(size_t)T_TOKENS * DIM] = (float)NEXP * aux;
            }
            __threadfence();
        }
    }
}

__global__ void scatter_kernel() {
    int t = blockIdx.x * 256 + threadIdx.x;
    if (t >= T_TOKENS) return;
#pragma unroll
    for (int k = 0; k < TOPK; k++) {
        int e   = g_topk_idx[t*2+k];
        int pos = atomicAdd(&g_cursor[e], 1);
        int r   = g_offsets[e] + pos;
        g_row_token[r]     = t;
        g_token_row[t*2+k] = r;
    }
}

// ---------------- grouped GEMM: mma.sync fp16, fp32 accum, cp.async 3-stage ----------------
// (R12/R14/R16-verified mainloop — DO NOT TOUCH)
// L1:  hidden = gelu(x @ w1^T + b1) -> g_hh (fp16)
// !L1: y      = hidden @ w2^T + b2  -> g_yh (fp16)
template <int KTOT, int NTOT, bool L1>
__global__ void __launch_bounds__(256, 2)
gemm_mma(const float* __restrict__ bias) {
    int tile = blockIdx.y;
    if (tile >= g_ntiles) return;
    int e     = g_tile_expert[tile];
    int row0  = g_tile_row[tile];
    int mrows = g_tile_m[tile];
    int n0    = blockIdx.x * BN;

    extern __shared__ char sm[];
    uint32_t sb = s2u(sm);

    int tid = threadIdx.x, lane = tid & 31, wid = tid >> 5;
    int wm = (wid & 1) * 64;
    int wn = (wid >> 1) * 32;

    const __half* A = L1 ? g_xh : g_hh;
    const __half* B = (L1 ? g_w1h : g_w2h) + ((size_t)e * NTOT + n0) * KTOT;
    const float* be = bias + (size_t)e * NTOT + n0;

    size_t aoff[2], boff[2];
    uint32_t smoffA[2], smoffB[2];
    uint32_t asz[2];
#pragma unroll
    for (int t = 0; t < 2; t++) {
        int idx = tid + 256 * t;
        int r = idx >> 2, c = idx & 3;
        bool ok = (r < mrows);
        size_t rowbase;
        if (L1) rowbase = ok ? (size_t)g_row_token[row0 + r] * KTOT : 0;
        else    rowbase = ok ? (size_t)(row0 + r) * KTOT : 0;
        aoff[t]   = rowbase + c * 8;
        smoffA[t] = (uint32_t)(r * ROWB + c * 16);
        asz[t]    = ok ? 16u : 0u;
        boff[t]   = (size_t)r * KTOT + c * 8;
        smoffB[t] = smoffA[t];
    }

    auto issue_stage = [&](int s, int kc) {
        int k0 = kc * BK;
        uint32_t base = sb + s * STAGE;
#pragma unroll
        for (int t = 0; t < 2; t++) {
            CPASYNC16(base + smoffA[t],           A + aoff[t] + k0, asz[t]);
            CPASYNC16(base + TILE_SZ + smoffB[t], B + boff[t] + k0, 16u);
        }
    };

    float acc[4][4][4];
#pragma unroll
    for (int i = 0; i < 4; i++)
#pragma unroll
        for (int j = 0; j < 4; j++)
#pragma unroll
            for (int q = 0; q < 4; q++) acc[i][j][q] = 0.f;

    auto compute = [&](int s) {
        uint32_t Ab = sb + s * STAGE;
#pragma unroll
        for (int h = 0; h < 2; h++) {
            int cb = 2 * h + (lane >> 4);
            int rA = wm + (lane & 15);
            uint32_t ah[4][4];
#pragma unroll
            for (int i = 0; i < 4; i++) {
                uint32_t ad = Ab + (uint32_t)((rA + i * 16) * ROWB + cb * 16);
                LDSM4(ah[i], ad);
            }
            int rB = wn + (lane & 15);
            uint32_t bh[2][4];
#pragma unroll
            for (int j = 0; j < 2; j++) {
                uint32_t bd = Ab + TILE_SZ +
                              (uint32_t)((rB + j * 16) * ROWB + cb * 16);
                LDSM4(bh[j], bd);
            }
#pragma unroll
            for (int i = 0; i < 4; i++)
#pragma unroll
                for (int j = 0; j < 4; j++) {
                    int jj = j >> 1, ss = j & 1;
                    MMA16816F16(acc[i][j], ah[i], bh[jj][ss], bh[jj][ss + 2]);
                }
        }
    };

    constexpr int NC = KTOT / BK;
    issue_stage(0, 0); CPCOMMIT();
    issue_stage(1, 1); CPCOMMIT();
    for (int c = 0; c < NC; c++) {
        CPWAIT1();
        __syncthreads();
        compute(c % NSTAGE);
        if (c + 2 < NC) issue_stage((c + 2) % NSTAGE, c + 2);
        CPCOMMIT();
    }

#pragma unroll
    for (int j = 0; j < 4; j++) {
        int colw = wn + j * 8 + 2 * (lane & 3);
        float b0 = __ldg(be + colw);
        float b1 = __ldg(be + colw + 1);
#pragma unroll
        for (int i = 0; i < 4; i++) {
#pragma unroll
            for (int rh = 0; rh < 2; rh++) {
                int m = wm + i * 16 + (lane >> 2) + rh * 8;
                if (m >= mrows) continue;
                float v0 = acc[i][j][rh * 2 + 0] + b0;
                float v1 = acc[i][j][rh * 2 + 1] + b1;
                size_t gbase = (size_t)(row0 + m) * NTOT + n0 + colw;
                if (L1) {
                    v0 = gelu_exact(v0);
                    v1 = gelu_exact(v1);
                    __half2 p = __floats2half2_rn(v0, v1);
                    *(uint32_t*)(g_hh + gbase) = *(uint32_t*)&p;
                } else {
                    __half2 p = __floats2half2_rn(v0, v1);
                    *(uint32_t*)(g_yh + gbase) = *(uint32_t*)&p;
                }
            }
        }
    }
}

// ---------------- deterministic gated combine (4 tokens/block) --------------
__global__ void combine_kernel(float* __restrict__ out) {
    int tb = blockIdx.x * 4;
#pragma unroll
    for (int q = 0; q < 4; q++) {
        int t = tb + q;
        int r0 = g_token_row[t*2+0], r1 = g_token_row[t*2+1];
        float g0 = g_topk_gate[t*2+0], g1 = g_topk_gate[t*2+1];
        const uint2* y0 = (const uint2*)(g_yh + (size_t)r0 * DIM);
        const uint2* y1 = (const uint2*)(g_yh + (size_t)r1 * DIM);
        float4* o = (float4*)(out + (size_t)t * DIM);
        int c = threadIdx.x;          // 256 threads x 4 halves = 1024 elems
        uint2 a = y0[c], b = y1[c];
        float2 a0 = __half22float2(*(__half2*)&a.x);
        float2 a1 = __half22float2(*(__half2*)&a.y);
        float2 b0 = __half22float2(*(__half2*)&b.x);
        float2 b1 = __half22float2(*(__half2*)&b.y);
        o[c] = make_float4(g0 * a0.x + g1 * b0.x, g0 * a0.y + g1 * b0.y,
                           g0 * a1.x + g1 * b1.x, g0 * a1.y + g1 * b1.y);
    }
}

// ---------------- launch ----------------
extern "C" void kernel_launch(void* const* d_in, const int* in_sizes, int n_in,
                              void* d_out, int out_size) {
    const float* x  = (const float*)d_in[0];
    const float* rw = (const float*)d_in[1];
    const float* w1 = (const float*)d_in[2];
    const float* b1 = (const float*)d_in[3];
    const float* w2 = (const float*)d_in[4];
    const float* b2 = (const float*)d_in[5];
    float* out = (float*)d_out;

    int write_aux = (out_size > T_TOKENS * DIM) ? 1 : 0;

    cudaFuncSetAttribute(gemm_mma<DIM, HIDDEN, true>,
                         cudaFuncAttributeMaxDynamicSharedMemorySize, SMEM_DYN);
    cudaFuncSetAttribute(gemm_mma<HIDDEN, DIM, false>,
                         cudaFuncAttributeMaxDynamicSharedMemorySize, SMEM_DYN);

    // fork-join: weight conversions overlapped with router/scatter chain.
    cudaStream_t side = 0;
    cudaEvent_t ev_fork = 0, ev_join = 0;
    bool forked =
        (cudaStreamCreateWithFlags(&side, cudaStreamNonBlocking) == cudaSuccess) &&
        (cudaEventCreateWithFlags(&ev_fork, cudaEventDisableTiming) == cudaSuccess) &&
        (cudaEventCreateWithFlags(&ev_join, cudaEventDisableTiming) == cudaSuccess);

    if (forked) {
        cudaEventRecord(ev_fork, 0);
        cudaStreamWaitEvent(side, ev_fork, 0);
        conv_kernel<<<592, 256, 0, side>>>((const float4*)w1, 0, NEXP * HIDDEN * DIM / 4);
        conv_kernel<<<592, 256, 0, side>>>((const float4*)w2, 1, NEXP * DIM * HIDDEN / 4);
        cudaEventRecord(ev_join, side);
    } else {
        conv_kernel<<<592, 256>>>((const float4*)w1, 0, NEXP * HIDDEN * DIM / 4);
        conv_kernel<<<592, 256>>>((const float4*)w2, 1, NEXP * DIM * HIDDEN / 4);
    }

    init_kernel<<<1, 32>>>();
    router_kernel<<<RT_GRID, RT_BLK>>>(x, rw, out, write_aux);   // schedule fused in last block
    scatter_kernel<<<(T_TOKENS + 255) / 256, 256>>>();

    if (forked) cudaStreamWaitEvent(0, ev_join, 0);   // join before L1

    gemm_mma<DIM, HIDDEN, true><<<dim3(HIDDEN / BN, MAXTILES), 256, SMEM_DYN>>>(b1);
    gemm_mma<HIDDEN, DIM, false><<<dim3(DIM / BN, MAXTILES), 256, SMEM_DYN>>>(b2);
    combine_kernel<<<T_TOKENS / 4, 256>>>(out);

    if (side)    cudaStreamDestroy(side);
    if (ev_fork) cudaEventDestroy(ev_fork);
    if (ev_join) cudaEventDestroy(ev_join);
}